// round 11
// baseline (speedup 1.0000x reference)
#include <cuda_runtime.h>
#include <math.h>

#define N_NODES 50000
#define N_EDGES 800000
#define N_GRAPHS 128
#define NEG_SLOPE 0.2f

// ---------------- scratch (device globals) ----------------
__device__ float g_el1[N_NODES * 3];
__device__ float g_er1[N_NODES * 3];
__device__ float g_x1[N_NODES * 96];      // post-relu layer-1 output

__device__ float g_el2[N_NODES * 3];
__device__ float g_er2[N_NODES * 3];
__device__ float g_x2[N_NODES * 192];     // pre-relu layer-2 output

__device__ float g_a[3 * N_EDGES];        // leaky logits [h][sorted p]
__device__ float g_max[N_NODES * 3];      // per (node,head) max logit

__device__ float g_w1al[30], g_w1ar[30];      // W1 @ al1 / ar1   [h][d<10]
__device__ float g_w2al[288], g_w2ar[288];    // W2 @ al2 / ar2   [h][k<96]

__device__ float g_pool[N_GRAPHS * 192];
__device__ float g_cnt[N_GRAPHS];

// CSR scratch
__device__ int g_deg[N_NODES];
__device__ int g_off[N_NODES + 1];
__device__ int g_cur[N_NODES];
__device__ int g_esrc[N_EDGES];
__device__ int g_edst[N_EDGES];

// ---------------- init ----------------
__global__ void k_init(const int* __restrict__ dummy) {
    int i = blockIdx.x * blockDim.x + threadIdx.x;
    if (i < N_NODES) g_deg[i] = 0;
    if (i < N_NODES * 3) g_max[i] = -INFINITY;
    if (i < N_GRAPHS * 192) g_pool[i] = 0.0f;
    if (i < N_GRAPHS)       g_cnt[i] = 0.0f;
}

// ---------------- CSR build (proven) ----------------
__global__ void k_hist(const int* __restrict__ dst) {
    int e = blockIdx.x * blockDim.x + threadIdx.x;
    if (e < N_EDGES) atomicAdd(&g_deg[dst[e]], 1);
}

#define SCAN_T 256
#define SCAN_CHUNK ((N_NODES + SCAN_T - 1) / SCAN_T)
__global__ void k_scan(const int* __restrict__ dst_unused) {
    __shared__ int psum[SCAN_T];
    int t = threadIdx.x;
    int lo = t * SCAN_CHUNK;
    int hi = (lo + SCAN_CHUNK < N_NODES) ? (lo + SCAN_CHUNK) : N_NODES;
    int s = 0;
    for (int n = lo; n < hi; n++) s += g_deg[n];
    psum[t] = s;
    __syncthreads();
    if (t == 0) {
        int run = 0;
        for (int i = 0; i < SCAN_T; i++) { int tmp = psum[i]; psum[i] = run; run += tmp; }
    }
    __syncthreads();
    int run = psum[t];
    for (int n = lo; n < hi; n++) {
        g_off[n] = run;
        g_cur[n] = run;
        run += g_deg[n];
    }
    if (t == 0) g_off[N_NODES] = N_EDGES;
}

__global__ void k_scatter(const int* __restrict__ src, const int* __restrict__ dst) {
    int e = blockIdx.x * blockDim.x + threadIdx.x;
    if (e < N_EDGES) {
        int d = dst[e];
        int p = atomicAdd(&g_cur[d], 1);
        g_esrc[p] = src[e];
        g_edst[p] = d;
    }
}

__global__ void k_cnt(const int* __restrict__ gid) {
    int n = blockIdx.x * blockDim.x + threadIdx.x;
    if (n < N_NODES) atomicAdd(&g_cnt[gid[n]], 1.0f);
}

// ---------------- helpers ----------------
__device__ __forceinline__ void atomicMaxF(float* addr, float v) {
    if (v >= 0.0f) atomicMax((int*)addr, __float_as_int(v));
    else           atomicMin((unsigned int*)addr, __float_as_uint(v));
}

// ---------------- precompute projected attention vectors ----------------
// w1al[h][d] = sum_j W1[d, h*32+j]*al1[h,j];  w2al[h][k] = sum_j W2[k, h*64+j]*al2[h,j]
__global__ void k_prew(const float* __restrict__ W1, const float* __restrict__ al1,
                       const float* __restrict__ ar1, const float* __restrict__ W2,
                       const float* __restrict__ al2, const float* __restrict__ ar2) {
    int t = threadIdx.x;   // one block of 288
    if (t < 30) {
        int h = t / 10, d = t - 10 * h;
        float sl = 0.f, sr = 0.f;
#pragma unroll
        for (int j = 0; j < 32; j++) {
            float w = W1[d * 96 + h * 32 + j];
            sl = fmaf(w, al1[h * 32 + j], sl);
            sr = fmaf(w, ar1[h * 32 + j], sr);
        }
        g_w1al[t] = sl; g_w1ar[t] = sr;
    }
    if (t < 288) {
        int h = t / 96, k = t - 96 * h;
        float sl = 0.f, sr = 0.f;
#pragma unroll 8
        for (int j = 0; j < 64; j++) {
            float w = W2[k * 192 + h * 64 + j];
            sl = fmaf(w, al2[h * 64 + j], sl);
            sr = fmaf(w, ar2[h * 64 + j], sr);
        }
        g_w2al[t] = sl; g_w2ar[t] = sr;
    }
}

// ---------------- layer 1 el/er directly from features ----------------
__global__ void k_el1(const float* __restrict__ feat) {
    int n = blockIdx.x * blockDim.x + threadIdx.x;
    if (n >= N_NODES) return;
    float f[10];
#pragma unroll
    for (int d = 0; d < 10; d++) f[d] = feat[n * 10 + d];
#pragma unroll
    for (int h = 0; h < 3; h++) {
        float el = 0.f, er = 0.f;
#pragma unroll
        for (int d = 0; d < 10; d++) {
            el = fmaf(f[d], g_w1al[h * 10 + d], el);
            er = fmaf(f[d], g_w1ar[h * 10 + d], er);
        }
        g_el1[n * 3 + h] = el;
        g_er1[n * 3 + h] = er;
    }
}

// ---------------- logits (proven form): thread per edge, 3 heads ----------------
__global__ void k_logits1(const int* __restrict__ a, const int* __restrict__ b) {
    int p = blockIdx.x * blockDim.x + threadIdx.x;
    if (p >= N_EDGES) return;
    int sv = g_esrc[p], dv = g_edst[p];
    float v0 = g_el1[sv * 3 + 0] + g_er1[dv * 3 + 0];
    float v1 = g_el1[sv * 3 + 1] + g_er1[dv * 3 + 1];
    float v2 = g_el1[sv * 3 + 2] + g_er1[dv * 3 + 2];
    v0 = (v0 > 0.f) ? v0 : NEG_SLOPE * v0;
    v1 = (v1 > 0.f) ? v1 : NEG_SLOPE * v1;
    v2 = (v2 > 0.f) ? v2 : NEG_SLOPE * v2;
    g_a[p]               = v0;
    g_a[N_EDGES + p]     = v1;
    g_a[2 * N_EDGES + p] = v2;
    atomicMaxF(&g_max[dv * 3 + 0], v0);
    atomicMaxF(&g_max[dv * 3 + 1], v1);
    atomicMaxF(&g_max[dv * 3 + 2], v2);
}

__global__ void k_logits2(const int* __restrict__ a, const int* __restrict__ b) {
    int p = blockIdx.x * blockDim.x + threadIdx.x;
    if (p >= N_EDGES) return;
    int sv = g_esrc[p], dv = g_edst[p];
    float v0 = g_el2[sv * 3 + 0] + g_er2[dv * 3 + 0];
    float v1 = g_el2[sv * 3 + 1] + g_er2[dv * 3 + 1];
    float v2 = g_el2[sv * 3 + 2] + g_er2[dv * 3 + 2];
    v0 = (v0 > 0.f) ? v0 : NEG_SLOPE * v0;
    v1 = (v1 > 0.f) ? v1 : NEG_SLOPE * v1;
    v2 = (v2 > 0.f) ? v2 : NEG_SLOPE * v2;
    g_a[p]               = v0;
    g_a[N_EDGES + p]     = v1;
    g_a[2 * N_EDGES + p] = v2;
    atomicMaxF(&g_max[dv * 3 + 0], v0);
    atomicMaxF(&g_max[dv * 3 + 1], v1);
    atomicMaxF(&g_max[dv * 3 + 2], v2);
}

// re-init g_max between layers
__global__ void k_remax(const int* __restrict__ dummy) {
    int i = blockIdx.x * blockDim.x + threadIdx.x;
    if (i < N_NODES * 3) g_max[i] = -INFINITY;
}

// ---------------- layer 1 fused: aggregate FEATURES (10-dim) then mini-GEMM ----
// warp per node; 6250 blocks x 8 warps exactly covers 50000 nodes (no early exit).
// lane l<30 owns (h=l/10, d=l%10); aggregates u1[h][d] = sum_e a_e^h feat[src][d].
// Then x1[n, h*32+j] = relu( sum_d u1[h][d] * W1[d, h*32+j] ).
__global__ void k_agg1f(const float* __restrict__ feat, const float* __restrict__ W1) {
    __shared__ float u1s[8][32];
    int wid = threadIdx.x >> 5, lane = threadIdx.x & 31;
    int n = blockIdx.x * 8 + wid;                 // < 50000 always
    int b0 = g_off[n], b1 = g_off[n + 1];
    int h = lane / 10; if (h > 2) h = 2;          // lanes 30,31 compute safely, unused
    int d = lane - 10 * ((lane < 30) ? (lane / 10) : 2);
    if (lane >= 30) d = 0;
    float mh = g_max[n * 3 + h];
    const float* ga = &g_a[h * N_EDGES];
    float s = 0.f, acc = 0.f;
    for (int p = b0; p < b1; p++) {
        int sv = g_esrc[p];
        float e = expf(ga[p] - mh);
        s += e;
        acc = fmaf(e, feat[sv * 10 + d], acc);
    }
    float inv = 1.0f / (s + 1e-16f);
    u1s[wid][lane] = acc * inv;
    __syncthreads();
    // mini-GEMM: each lane produces outputs o = lane, lane+32, lane+64
#pragma unroll
    for (int t = 0; t < 3; t++) {
        int o = lane + 32 * t;
        int hh = o >> 5;
        float x = 0.f;
#pragma unroll
        for (int dd = 0; dd < 10; dd++)
            x = fmaf(u1s[wid][hh * 10 + dd], __ldg(&W1[dd * 96 + o]), x);
        g_x1[n * 96 + o] = fmaxf(x, 0.f);         // relu fused
    }
}

// ---------------- layer 2 el/er directly from x1 ----------------
__global__ void k_el2(const int* __restrict__ dummy) {
    int i = blockIdx.x * blockDim.x + threadIdx.x;
    if (i >= N_NODES * 3) return;
    int n = i / 3, h = i - n * 3;
    float el = 0.f, er = 0.f;
#pragma unroll 8
    for (int k = 0; k < 96; k++) {
        float x = g_x1[n * 96 + k];
        el = fmaf(x, g_w2al[h * 96 + k], el);
        er = fmaf(x, g_w2ar[h * 96 + k], er);
    }
    g_el2[i] = el; g_er2[i] = er;
}

// ---------------- layer 2 fused: aggregate x1 rows (384B/edge) + block GEMM ----
// warp per node (agg), then 8-node block GEMM u2[8][288] @ W2 -> x2[8][192].
__global__ void k_agg2f(const float* __restrict__ W2) {
    __shared__ float u2s[8][288];
    int wid = threadIdx.x >> 5, lane = threadIdx.x & 31;
    int nb = blockIdx.x * 8;
    int n = nb + wid;
    int b0 = g_off[n], b1 = g_off[n + 1];
    float m0 = g_max[n * 3 + 0], m1 = g_max[n * 3 + 1], m2 = g_max[n * 3 + 2];
    float s0 = 0.f, s1 = 0.f, s2 = 0.f;
    float a00 = 0.f, a01 = 0.f, a02 = 0.f;   // head0 dims lane, lane+32, lane+64
    float a10 = 0.f, a11 = 0.f, a12 = 0.f;
    float a20 = 0.f, a21 = 0.f, a22 = 0.f;
    for (int p = b0; p < b1; p++) {
        int sv = g_esrc[p];
        float e0 = expf(g_a[p] - m0);
        float e1 = expf(g_a[N_EDGES + p] - m1);
        float e2 = expf(g_a[2 * N_EDGES + p] - m2);
        const float* xr = &g_x1[sv * 96];
        float x0 = xr[lane], x1v = xr[lane + 32], x2v = xr[lane + 64];
        a00 = fmaf(e0, x0, a00); a01 = fmaf(e0, x1v, a01); a02 = fmaf(e0, x2v, a02);
        a10 = fmaf(e1, x0, a10); a11 = fmaf(e1, x1v, a11); a12 = fmaf(e1, x2v, a12);
        a20 = fmaf(e2, x0, a20); a21 = fmaf(e2, x1v, a21); a22 = fmaf(e2, x2v, a22);
        s0 += e0; s1 += e1; s2 += e2;
    }
    float i0 = 1.0f / (s0 + 1e-16f);
    float i1 = 1.0f / (s1 + 1e-16f);
    float i2 = 1.0f / (s2 + 1e-16f);
    u2s[wid][lane]            = a00 * i0;
    u2s[wid][lane + 32]       = a01 * i0;
    u2s[wid][lane + 64]       = a02 * i0;
    u2s[wid][96 + lane]       = a10 * i1;
    u2s[wid][96 + lane + 32]  = a11 * i1;
    u2s[wid][96 + lane + 64]  = a12 * i1;
    u2s[wid][192 + lane]      = a20 * i2;
    u2s[wid][192 + lane + 32] = a21 * i2;
    u2s[wid][192 + lane + 64] = a22 * i2;
    __syncthreads();
    // block GEMM: x2[nb+i, o] = sum_k u2s[i][h*96+k] * W2[k*192+o], h = o/64
    int o = threadIdx.x;   // 0..255; only o<192 active
    if (o < 192) {
        int hbase = (o >> 6) * 96;
        float acc[8];
#pragma unroll
        for (int i = 0; i < 8; i++) acc[i] = 0.f;
        for (int k = 0; k < 96; k++) {
            float w = __ldg(&W2[k * 192 + o]);
#pragma unroll
            for (int i = 0; i < 8; i++)
                acc[i] = fmaf(u2s[i][hbase + k], w, acc[i]);
        }
#pragma unroll
        for (int i = 0; i < 8; i++)
            g_x2[(nb + i) * 192 + o] = acc[i];
    }
}

// ---------------- pooling (proven; relu applied here) ----------------
#define PNP 4
__global__ void k_pool(const int* __restrict__ gid) {
    int t = blockIdx.x * blockDim.x + threadIdx.x;
    int groups = (N_NODES + PNP - 1) / PNP;
    if (t >= groups * 192) return;
    int gidx = t / 192, j = t - gidx * 192;
    int n0 = gidx * PNP;
    int n1 = (n0 + PNP < N_NODES) ? (n0 + PNP) : N_NODES;
    float acc = 0.f;
    int cur = gid[n0];
    for (int n = n0; n < n1; n++) {
        int g = gid[n];
        if (g != cur) {
            atomicAdd(&g_pool[cur * 192 + j], acc);
            acc = 0.f; cur = g;
        }
        acc += fmaxf(g_x2[n * 192 + j], 0.f);
    }
    atomicAdd(&g_pool[cur * 192 + j], acc);
}

// ---------------- final MLP (proven) ----------------
__global__ void k_mlp(const float* __restrict__ d1w, const float* __restrict__ d1b,
                      const float* __restrict__ d2w, const float* __restrict__ d2b,
                      float* __restrict__ out) {
    int g = blockIdx.x;
    int j = threadIdx.x;  // 0..63
    __shared__ float ps[192];
    __shared__ float hred[64];
    float inv = 1.0f / fmaxf(g_cnt[g], 1.0f);
    for (int k = j; k < 192; k += 64) ps[k] = g_pool[g * 192 + k] * inv;
    __syncthreads();
    float acc = d1b[j];
#pragma unroll 8
    for (int k = 0; k < 192; k++) acc = fmaf(ps[k], __ldg(&d1w[k * 64 + j]), acc);
    acc = fmaxf(acc, 0.f);
    hred[j] = acc * __ldg(&d2w[j]);
    __syncthreads();
    for (int s = 32; s > 0; s >>= 1) {
        if (j < s) hred[j] += hred[j + s];
        __syncthreads();
    }
    if (j == 0) out[g] = hred[0] + d2b[0];
}

// ---------------- launch ----------------
extern "C" void kernel_launch(void* const* d_in, const int* in_sizes, int n_in,
                              void* d_out, int out_size) {
    const float* feature = (const float*)d_in[0];
    const int*   src     = (const int*)d_in[1];
    const int*   dst     = (const int*)d_in[2];
    const int*   gid     = (const int*)d_in[3];
    const float* W1      = (const float*)d_in[4];
    const float* al1     = (const float*)d_in[5];
    const float* ar1     = (const float*)d_in[6];
    const float* W2      = (const float*)d_in[7];
    const float* al2     = (const float*)d_in[8];
    const float* ar2     = (const float*)d_in[9];
    const float* d1w     = (const float*)d_in[10];
    const float* d1b     = (const float*)d_in[11];
    const float* d2w     = (const float*)d_in[12];
    const float* d2b     = (const float*)d_in[13];
    float* out = (float*)d_out;

    // init + CSR build + projections
    k_init<<<(N_NODES * 3 + 255) / 256, 256>>>(dst);
    k_hist<<<(N_EDGES + 255) / 256, 256>>>(dst);
    k_scan<<<1, SCAN_T>>>(dst);
    k_scatter<<<(N_EDGES + 255) / 256, 256>>>(src, dst);
    k_cnt<<<(N_NODES + 255) / 256, 256>>>(gid);
    k_prew<<<1, 288>>>(W1, al1, ar1, W2, al2, ar2);

    // ---- layer 1 ----
    k_el1<<<(N_NODES + 255) / 256, 256>>>(feature);
    k_logits1<<<(N_EDGES + 255) / 256, 256>>>(src, dst);
    k_agg1f<<<N_NODES / 8, 256>>>(feature, W1);     // 6250 full blocks

    // ---- layer 2 ----
    k_el2<<<(N_NODES * 3 + 255) / 256, 256>>>(src);
    k_remax<<<(N_NODES * 3 + 255) / 256, 256>>>(dst);
    k_logits2<<<(N_EDGES + 255) / 256, 256>>>(src, dst);
    k_agg2f<<<N_NODES / 8, 256>>>(W2);              // 6250 full blocks

    // ---- pool + MLP ----
    {
        int groups = (N_NODES + PNP - 1) / PNP;
        k_pool<<<(groups * 192 + 255) / 256, 256>>>(gid);
    }
    k_mlp<<<N_GRAPHS, 64>>>(d1w, d1b, d2w, d2b, out);
}

// round 12
// speedup vs baseline: 1.2353x; 1.2353x over previous
#include <cuda_runtime.h>
#include <math.h>

#define N_NODES 50000
#define N_EDGES 800000
#define N_GRAPHS 128
#define NEG_SLOPE 0.2f

// ---------------- scratch (device globals) ----------------
__device__ float g_z1[N_NODES * 96];
__device__ float g_el1[N_NODES * 3];
__device__ float g_er1[N_NODES * 3];
__device__ float g_x1[N_NODES * 96];      // POST-relu layer-1 output

__device__ float g_el2[N_NODES * 3];
__device__ float g_er2[N_NODES * 3];
__device__ float g_u2[N_NODES * 288];     // aggregated relu(x1) per head [n][h*96+k]
__device__ float g_x2[N_NODES * 192];     // pre-relu layer-2 output

__device__ float g_a[3 * N_EDGES];        // leaky logits [h][sorted p]
__device__ float g_max[N_NODES * 3];      // per (node,head) max logit

__device__ float g_w2al[288], g_w2ar[288];    // W2 @ al2 / ar2   [h][k<96]

__device__ float g_pool[N_GRAPHS * 192];
__device__ float g_cnt[N_GRAPHS];

// CSR scratch
__device__ int g_deg[N_NODES];
__device__ int g_off[N_NODES + 1];
__device__ int g_cur[N_NODES];
__device__ int g_esrc[N_EDGES];
__device__ int g_edst[N_EDGES];

// ---------------- init ----------------
__global__ void k_init(const int* __restrict__ dummy) {
    int i = blockIdx.x * blockDim.x + threadIdx.x;
    if (i < N_NODES) g_deg[i] = 0;
    if (i < N_NODES * 3) g_max[i] = -INFINITY;
    if (i < N_GRAPHS * 192) g_pool[i] = 0.0f;
    if (i < N_GRAPHS)       g_cnt[i] = 0.0f;
}

// ---------------- CSR build (proven) ----------------
__global__ void k_hist(const int* __restrict__ dst) {
    int e = blockIdx.x * blockDim.x + threadIdx.x;
    if (e < N_EDGES) atomicAdd(&g_deg[dst[e]], 1);
}

#define SCAN_T 256
#define SCAN_CHUNK ((N_NODES + SCAN_T - 1) / SCAN_T)
__global__ void k_scan(const int* __restrict__ dst_unused) {
    __shared__ int psum[SCAN_T];
    int t = threadIdx.x;
    int lo = t * SCAN_CHUNK;
    int hi = (lo + SCAN_CHUNK < N_NODES) ? (lo + SCAN_CHUNK) : N_NODES;
    int s = 0;
    for (int n = lo; n < hi; n++) s += g_deg[n];
    psum[t] = s;
    __syncthreads();
    if (t == 0) {
        int run = 0;
        for (int i = 0; i < SCAN_T; i++) { int tmp = psum[i]; psum[i] = run; run += tmp; }
    }
    __syncthreads();
    int run = psum[t];
    for (int n = lo; n < hi; n++) {
        g_off[n] = run;
        g_cur[n] = run;
        run += g_deg[n];
    }
    if (t == 0) g_off[N_NODES] = N_EDGES;
}

__global__ void k_scatter(const int* __restrict__ src, const int* __restrict__ dst) {
    int e = blockIdx.x * blockDim.x + threadIdx.x;
    if (e < N_EDGES) {
        int d = dst[e];
        int p = atomicAdd(&g_cur[d], 1);
        g_esrc[p] = src[e];
        g_edst[p] = d;
    }
}

__global__ void k_cnt(const int* __restrict__ gid) {
    int n = blockIdx.x * blockDim.x + threadIdx.x;
    if (n < N_NODES) atomicAdd(&g_cnt[gid[n]], 1.0f);
}

// ---------------- helpers ----------------
__device__ __forceinline__ void atomicMaxF(float* addr, float v) {
    if (v >= 0.0f) atomicMax((int*)addr, __float_as_int(v));
    else           atomicMin((unsigned int*)addr, __float_as_uint(v));
}

// ---------------- precompute W2-projected attention vectors ----------------
__global__ void k_prew(const float* __restrict__ W2, const float* __restrict__ al2,
                       const float* __restrict__ ar2) {
    int t = threadIdx.x;   // 288 threads
    if (t < 288) {
        int h = t / 96, k = t - 96 * h;
        float sl = 0.f, sr = 0.f;
#pragma unroll 8
        for (int j = 0; j < 64; j++) {
            float w = W2[k * 192 + h * 64 + j];
            sl = fmaf(w, al2[h * 64 + j], sl);
            sr = fmaf(w, ar2[h * 64 + j], sr);
        }
        g_w2al[t] = sl; g_w2ar[t] = sr;
    }
}

// ---------------- layer 1: z1 = feat @ W1, el1/er1 (R10-proven) ----------------
__global__ void k_layer1_z(const float* __restrict__ feat, const float* __restrict__ W1,
                           const float* __restrict__ al1, const float* __restrict__ ar1) {
    int n = blockIdx.x * blockDim.x + threadIdx.x;
    if (n >= N_NODES) return;
    float f[10];
#pragma unroll
    for (int k = 0; k < 10; k++) f[k] = feat[n * 10 + k];
    float el[3] = {0.f, 0.f, 0.f}, er[3] = {0.f, 0.f, 0.f};
#pragma unroll 4
    for (int o = 0; o < 96; o++) {
        float acc = 0.f;
#pragma unroll
        for (int k = 0; k < 10; k++) acc = fmaf(f[k], __ldg(&W1[k * 96 + o]), acc);
        g_z1[n * 96 + o] = acc;
        int h = o >> 5, d = o & 31;
        el[h] = fmaf(acc, __ldg(&al1[h * 32 + d]), el[h]);
        er[h] = fmaf(acc, __ldg(&ar1[h * 32 + d]), er[h]);
    }
#pragma unroll
    for (int h = 0; h < 3; h++) { g_el1[n * 3 + h] = el[h]; g_er1[n * 3 + h] = er[h]; }
}

// ---------------- logits (R10-proven): thread per edge, 3 heads ----------------
__global__ void k_logits1(const int* __restrict__ a, const int* __restrict__ b) {
    int p = blockIdx.x * blockDim.x + threadIdx.x;
    if (p >= N_EDGES) return;
    int sv = g_esrc[p], dv = g_edst[p];
    float v0 = g_el1[sv * 3 + 0] + g_er1[dv * 3 + 0];
    float v1 = g_el1[sv * 3 + 1] + g_er1[dv * 3 + 1];
    float v2 = g_el1[sv * 3 + 2] + g_er1[dv * 3 + 2];
    v0 = (v0 > 0.f) ? v0 : NEG_SLOPE * v0;
    v1 = (v1 > 0.f) ? v1 : NEG_SLOPE * v1;
    v2 = (v2 > 0.f) ? v2 : NEG_SLOPE * v2;
    g_a[p]               = v0;
    g_a[N_EDGES + p]     = v1;
    g_a[2 * N_EDGES + p] = v2;
    atomicMaxF(&g_max[dv * 3 + 0], v0);
    atomicMaxF(&g_max[dv * 3 + 1], v1);
    atomicMaxF(&g_max[dv * 3 + 2], v2);
}

__global__ void k_logits2(const int* __restrict__ a, const int* __restrict__ b) {
    int p = blockIdx.x * blockDim.x + threadIdx.x;
    if (p >= N_EDGES) return;
    int sv = g_esrc[p], dv = g_edst[p];
    float v0 = g_el2[sv * 3 + 0] + g_er2[dv * 3 + 0];
    float v1 = g_el2[sv * 3 + 1] + g_er2[dv * 3 + 1];
    float v2 = g_el2[sv * 3 + 2] + g_er2[dv * 3 + 2];
    v0 = (v0 > 0.f) ? v0 : NEG_SLOPE * v0;
    v1 = (v1 > 0.f) ? v1 : NEG_SLOPE * v1;
    v2 = (v2 > 0.f) ? v2 : NEG_SLOPE * v2;
    g_a[p]               = v0;
    g_a[N_EDGES + p]     = v1;
    g_a[2 * N_EDGES + p] = v2;
    atomicMaxF(&g_max[dv * 3 + 0], v0);
    atomicMaxF(&g_max[dv * 3 + 1], v1);
    atomicMaxF(&g_max[dv * 3 + 2], v2);
}

// re-init g_max between layers
__global__ void k_remax(const int* __restrict__ dummy) {
    int i = blockIdx.x * blockDim.x + threadIdx.x;
    if (i < N_NODES * 3) g_max[i] = -INFINITY;
}

// ---------------- aggregation layer 1 (R10-proven; now stores relu) ----------------
__global__ void k_agg1(const int* __restrict__ dummy) {
    int n = (blockIdx.x * blockDim.x + threadIdx.x) >> 5;
    if (n >= N_NODES) return;
    int lane = threadIdx.x & 31;
    int b0 = g_off[n], b1 = g_off[n + 1];
    float m0 = g_max[n * 3 + 0], m1 = g_max[n * 3 + 1], m2 = g_max[n * 3 + 2];
    float s0 = 0.f, s1 = 0.f, s2 = 0.f;
    float a0 = 0.f, a1 = 0.f, a2 = 0.f;
#pragma unroll 2
    for (int p = b0; p < b1; p++) {
        int sv = g_esrc[p];
        float e0 = expf(g_a[p] - m0);
        float e1 = expf(g_a[N_EDGES + p] - m1);
        float e2 = expf(g_a[2 * N_EDGES + p] - m2);
        const float* zr = &g_z1[sv * 96];
        a0 = fmaf(e0, zr[lane], a0);
        a1 = fmaf(e1, zr[lane + 32], a1);
        a2 = fmaf(e2, zr[lane + 64], a2);
        s0 += e0; s1 += e1; s2 += e2;
    }
    // relu fused: downstream (el2, agg2, GEMM) all consume relu(x1)
    g_x1[n * 96 + lane]      = fmaxf(a0 / (s0 + 1e-16f), 0.f);
    g_x1[n * 96 + lane + 32] = fmaxf(a1 / (s1 + 1e-16f), 0.f);
    g_x1[n * 96 + lane + 64] = fmaxf(a2 / (s2 + 1e-16f), 0.f);
}

// ---------------- layer 2 el/er directly from relu(x1) (commuted; R11-proven) ----
__global__ void k_el2(const int* __restrict__ dummy) {
    int i = blockIdx.x * blockDim.x + threadIdx.x;
    if (i >= N_NODES * 3) return;
    int n = i / 3, h = i - n * 3;
    float el = 0.f, er = 0.f;
#pragma unroll 8
    for (int k = 0; k < 96; k++) {
        float x = g_x1[n * 96 + k];
        el = fmaf(x, g_w2al[h * 96 + k], el);
        er = fmaf(x, g_w2ar[h * 96 + k], er);
    }
    g_el2[i] = el; g_er2[i] = er;
}

// ---------------- aggregation layer 2: warp per node over relu(x1) rows ----------
// 384 B/edge (vs 768 for z2). Warp-independent, no syncs. 9 accumulators.
__global__ void k_agg2u(const int* __restrict__ dummy) {
    int n = (blockIdx.x * blockDim.x + threadIdx.x) >> 5;
    if (n >= N_NODES) return;
    int lane = threadIdx.x & 31;
    int b0 = g_off[n], b1 = g_off[n + 1];
    float m0 = g_max[n * 3 + 0], m1 = g_max[n * 3 + 1], m2 = g_max[n * 3 + 2];
    float s0 = 0.f, s1 = 0.f, s2 = 0.f;
    float a00 = 0.f, a01 = 0.f, a02 = 0.f;
    float a10 = 0.f, a11 = 0.f, a12 = 0.f;
    float a20 = 0.f, a21 = 0.f, a22 = 0.f;
#pragma unroll 2
    for (int p = b0; p < b1; p++) {
        int sv = g_esrc[p];
        float e0 = expf(g_a[p] - m0);
        float e1 = expf(g_a[N_EDGES + p] - m1);
        float e2 = expf(g_a[2 * N_EDGES + p] - m2);
        const float* xr = &g_x1[sv * 96];
        float x0 = xr[lane], x1v = xr[lane + 32], x2v = xr[lane + 64];
        a00 = fmaf(e0, x0, a00); a01 = fmaf(e0, x1v, a01); a02 = fmaf(e0, x2v, a02);
        a10 = fmaf(e1, x0, a10); a11 = fmaf(e1, x1v, a11); a12 = fmaf(e1, x2v, a12);
        a20 = fmaf(e2, x0, a20); a21 = fmaf(e2, x1v, a21); a22 = fmaf(e2, x2v, a22);
        s0 += e0; s1 += e1; s2 += e2;
    }
    float i0 = 1.0f / (s0 + 1e-16f);
    float i1 = 1.0f / (s1 + 1e-16f);
    float i2 = 1.0f / (s2 + 1e-16f);
    float* u = &g_u2[n * 288];
    u[lane]            = a00 * i0;
    u[lane + 32]       = a01 * i0;
    u[lane + 64]       = a02 * i0;
    u[96 + lane]       = a10 * i1;
    u[96 + lane + 32]  = a11 * i1;
    u[96 + lane + 64]  = a12 * i1;
    u[192 + lane]      = a20 * i2;
    u[192 + lane + 32] = a21 * i2;
    u[192 + lane + 64] = a22 * i2;
}

// ---------------- layer 2 GEMM on aggregated rows: x2 = u2 @ W2 per head ----------
// proven 8-nodes/block structure; o<192 threads; h = o/64, inner k<96.
#define GT 8
__global__ void k_gemm2(const float* __restrict__ W2) {
    __shared__ float us[GT][289];
    int o = threadIdx.x;            // 0..191
    int base = blockIdx.x * GT;     // 6250 full blocks
    for (int idx = threadIdx.x; idx < GT * 288; idx += 192) {
        int i = idx / 288, k = idx - i * 288;
        us[i][k] = g_u2[(base + i) * 288 + k];
    }
    __syncthreads();
    int hbase = (o >> 6) * 96;
    float acc[GT];
#pragma unroll
    for (int i = 0; i < GT; i++) acc[i] = 0.f;
    for (int k = 0; k < 96; k++) {
        float w = __ldg(&W2[k * 192 + o]);
#pragma unroll
        for (int i = 0; i < GT; i++) acc[i] = fmaf(us[i][hbase + k], w, acc[i]);
    }
#pragma unroll
    for (int i = 0; i < GT; i++)
        g_x2[(base + i) * 192 + o] = acc[i];
}

// ---------------- pooling (proven; relu applied here) ----------------
#define PNP 4
__global__ void k_pool(const int* __restrict__ gid) {
    int t = blockIdx.x * blockDim.x + threadIdx.x;
    int groups = (N_NODES + PNP - 1) / PNP;
    if (t >= groups * 192) return;
    int gidx = t / 192, j = t - gidx * 192;
    int n0 = gidx * PNP;
    int n1 = (n0 + PNP < N_NODES) ? (n0 + PNP) : N_NODES;
    float acc = 0.f;
    int cur = gid[n0];
    for (int n = n0; n < n1; n++) {
        int g = gid[n];
        if (g != cur) {
            atomicAdd(&g_pool[cur * 192 + j], acc);
            acc = 0.f; cur = g;
        }
        acc += fmaxf(g_x2[n * 192 + j], 0.f);
    }
    atomicAdd(&g_pool[cur * 192 + j], acc);
}

// ---------------- final MLP (proven) ----------------
__global__ void k_mlp(const float* __restrict__ d1w, const float* __restrict__ d1b,
                      const float* __restrict__ d2w, const float* __restrict__ d2b,
                      float* __restrict__ out) {
    int g = blockIdx.x;
    int j = threadIdx.x;  // 0..63
    __shared__ float ps[192];
    __shared__ float hred[64];
    float inv = 1.0f / fmaxf(g_cnt[g], 1.0f);
    for (int k = j; k < 192; k += 64) ps[k] = g_pool[g * 192 + k] * inv;
    __syncthreads();
    float acc = d1b[j];
#pragma unroll 8
    for (int k = 0; k < 192; k++) acc = fmaf(ps[k], __ldg(&d1w[k * 64 + j]), acc);
    acc = fmaxf(acc, 0.f);
    hred[j] = acc * __ldg(&d2w[j]);
    __syncthreads();
    for (int s = 32; s > 0; s >>= 1) {
        if (j < s) hred[j] += hred[j + s];
        __syncthreads();
    }
    if (j == 0) out[g] = hred[0] + d2b[0];
}

// ---------------- launch ----------------
extern "C" void kernel_launch(void* const* d_in, const int* in_sizes, int n_in,
                              void* d_out, int out_size) {
    const float* feature = (const float*)d_in[0];
    const int*   src     = (const int*)d_in[1];
    const int*   dst     = (const int*)d_in[2];
    const int*   gid     = (const int*)d_in[3];
    const float* W1      = (const float*)d_in[4];
    const float* al1     = (const float*)d_in[5];
    const float* ar1     = (const float*)d_in[6];
    const float* W2      = (const float*)d_in[7];
    const float* al2     = (const float*)d_in[8];
    const float* ar2     = (const float*)d_in[9];
    const float* d1w     = (const float*)d_in[10];
    const float* d1b     = (const float*)d_in[11];
    const float* d2w     = (const float*)d_in[12];
    const float* d2b     = (const float*)d_in[13];
    float* out = (float*)d_out;

    // init + CSR build + projections
    k_init<<<(N_NODES * 3 + 255) / 256, 256>>>(dst);
    k_hist<<<(N_EDGES + 255) / 256, 256>>>(dst);
    k_scan<<<1, SCAN_T>>>(dst);
    k_scatter<<<(N_EDGES + 255) / 256, 256>>>(src, dst);
    k_cnt<<<(N_NODES + 255) / 256, 256>>>(gid);
    k_prew<<<1, 288>>>(W2, al2, ar2);

    // ---- layer 1 (R10-proven path) ----
    k_layer1_z<<<(N_NODES + 127) / 128, 128>>>(feature, W1, al1, ar1);
    k_logits1<<<(N_EDGES + 255) / 256, 256>>>(src, dst);
    k_agg1<<<(N_NODES * 32 + 255) / 256, 256>>>(src);

    // ---- layer 2 (commuted GEMM; warp-independent agg) ----
    k_el2<<<(N_NODES * 3 + 255) / 256, 256>>>(src);
    k_remax<<<(N_NODES * 3 + 255) / 256, 256>>>(dst);
    k_logits2<<<(N_EDGES + 255) / 256, 256>>>(src, dst);
    k_agg2u<<<(N_NODES * 32 + 255) / 256, 256>>>(src);
    k_gemm2<<<N_NODES / GT, 192>>>(W2);

    // ---- pool + MLP ----
    {
        int groups = (N_NODES + PNP - 1) / PNP;
        k_pool<<<(groups * 192 + 255) / 256, 256>>>(gid);
    }
    k_mlp<<<N_GRAPHS, 64>>>(d1w, d1b, d2w, d2b, out);
}

// round 13
// speedup vs baseline: 1.2736x; 1.0310x over previous
#include <cuda_runtime.h>
#include <math.h>

#define N_NODES 50000
#define N_EDGES 800000
#define N_GRAPHS 128
#define NEG_SLOPE 0.2f

// ---------------- scratch (device globals) ----------------
__device__ __align__(16) float g_z1[N_NODES * 96];
__device__ float g_el1[N_NODES * 3];
__device__ float g_er1[N_NODES * 3];
__device__ __align__(16) float g_x1[N_NODES * 96];    // POST-relu layer-1 output

__device__ float g_el2[N_NODES * 3];
__device__ float g_er2[N_NODES * 3];
__device__ __align__(16) float g_u2[N_NODES * 288];   // aggregated relu(x1) per head

__device__ __align__(16) float4 g_a4[N_EDGES];        // {v0,v1,v2, bits(src)} per sorted edge
__device__ float g_max[N_NODES * 3];

__device__ float g_w2al[288], g_w2ar[288];            // W2 @ al2 / ar2

__device__ float g_pool[N_GRAPHS * 192];
__device__ float g_cnt[N_GRAPHS];

// CSR scratch
__device__ int g_deg[N_NODES];
__device__ int g_off[N_NODES + 1];
__device__ int g_cur[N_NODES];
__device__ int g_esrc[N_EDGES];
__device__ int g_edst[N_EDGES];

// ---------------- init ----------------
__global__ void k_init(const int* __restrict__ dummy) {
    int i = blockIdx.x * blockDim.x + threadIdx.x;
    if (i < N_NODES) g_deg[i] = 0;
    if (i < N_NODES * 3) g_max[i] = -INFINITY;
    if (i < N_GRAPHS * 192) g_pool[i] = 0.0f;
    if (i < N_GRAPHS)       g_cnt[i] = 0.0f;
}

// ---------------- CSR build (proven) ----------------
__global__ void k_hist(const int* __restrict__ dst) {
    int e = blockIdx.x * blockDim.x + threadIdx.x;
    if (e < N_EDGES) atomicAdd(&g_deg[dst[e]], 1);
}

#define SCAN_T 256
#define SCAN_CHUNK ((N_NODES + SCAN_T - 1) / SCAN_T)
__global__ void k_scan(const int* __restrict__ dst_unused) {
    __shared__ int psum[SCAN_T];
    int t = threadIdx.x;
    int lo = t * SCAN_CHUNK;
    int hi = (lo + SCAN_CHUNK < N_NODES) ? (lo + SCAN_CHUNK) : N_NODES;
    int s = 0;
    for (int n = lo; n < hi; n++) s += g_deg[n];
    psum[t] = s;
    __syncthreads();
    if (t == 0) {
        int run = 0;
        for (int i = 0; i < SCAN_T; i++) { int tmp = psum[i]; psum[i] = run; run += tmp; }
    }
    __syncthreads();
    int run = psum[t];
    for (int n = lo; n < hi; n++) {
        g_off[n] = run;
        g_cur[n] = run;
        run += g_deg[n];
    }
    if (t == 0) g_off[N_NODES] = N_EDGES;
}

__global__ void k_scatter(const int* __restrict__ src, const int* __restrict__ dst) {
    int e = blockIdx.x * blockDim.x + threadIdx.x;
    if (e < N_EDGES) {
        int d = dst[e];
        int p = atomicAdd(&g_cur[d], 1);
        g_esrc[p] = src[e];
        g_edst[p] = d;
    }
}

__global__ void k_cnt(const int* __restrict__ gid) {
    int n = blockIdx.x * blockDim.x + threadIdx.x;
    if (n < N_NODES) atomicAdd(&g_cnt[gid[n]], 1.0f);
}

// ---------------- helpers ----------------
__device__ __forceinline__ void atomicMaxF(float* addr, float v) {
    if (v >= 0.0f) atomicMax((int*)addr, __float_as_int(v));
    else           atomicMin((unsigned int*)addr, __float_as_uint(v));
}

// ---------------- precompute W2-projected attention vectors (proven) ----------------
__global__ void k_prew(const float* __restrict__ W2, const float* __restrict__ al2,
                       const float* __restrict__ ar2) {
    int t = threadIdx.x;   // 288 threads
    if (t < 288) {
        int h = t / 96, k = t - 96 * h;
        float sl = 0.f, sr = 0.f;
#pragma unroll 8
        for (int j = 0; j < 64; j++) {
            float w = W2[k * 192 + h * 64 + j];
            sl = fmaf(w, al2[h * 64 + j], sl);
            sr = fmaf(w, ar2[h * 64 + j], sr);
        }
        g_w2al[t] = sl; g_w2ar[t] = sr;
    }
}

// ---------------- layer 1: z1 = feat @ W1, el1/er1 (proven) ----------------
__global__ void k_layer1_z(const float* __restrict__ feat, const float* __restrict__ W1,
                           const float* __restrict__ al1, const float* __restrict__ ar1) {
    int n = blockIdx.x * blockDim.x + threadIdx.x;
    if (n >= N_NODES) return;
    float f[10];
#pragma unroll
    for (int k = 0; k < 10; k++) f[k] = feat[n * 10 + k];
    float el[3] = {0.f, 0.f, 0.f}, er[3] = {0.f, 0.f, 0.f};
#pragma unroll 4
    for (int o = 0; o < 96; o++) {
        float acc = 0.f;
#pragma unroll
        for (int k = 0; k < 10; k++) acc = fmaf(f[k], __ldg(&W1[k * 96 + o]), acc);
        g_z1[n * 96 + o] = acc;
        int h = o >> 5, d = o & 31;
        el[h] = fmaf(acc, __ldg(&al1[h * 32 + d]), el[h]);
        er[h] = fmaf(acc, __ldg(&ar1[h * 32 + d]), er[h]);
    }
#pragma unroll
    for (int h = 0; h < 3; h++) { g_el1[n * 3 + h] = el[h]; g_er1[n * 3 + h] = er[h]; }
}

// ---------------- logits: thread per edge, 3 heads, packed float4 store ----------
__global__ void k_logits1(const int* __restrict__ a, const int* __restrict__ b) {
    int p = blockIdx.x * blockDim.x + threadIdx.x;
    if (p >= N_EDGES) return;
    int sv = g_esrc[p], dv = g_edst[p];
    float v0 = g_el1[sv * 3 + 0] + g_er1[dv * 3 + 0];
    float v1 = g_el1[sv * 3 + 1] + g_er1[dv * 3 + 1];
    float v2 = g_el1[sv * 3 + 2] + g_er1[dv * 3 + 2];
    v0 = (v0 > 0.f) ? v0 : NEG_SLOPE * v0;
    v1 = (v1 > 0.f) ? v1 : NEG_SLOPE * v1;
    v2 = (v2 > 0.f) ? v2 : NEG_SLOPE * v2;
    g_a4[p] = make_float4(v0, v1, v2, __int_as_float(sv));
    atomicMaxF(&g_max[dv * 3 + 0], v0);
    atomicMaxF(&g_max[dv * 3 + 1], v1);
    atomicMaxF(&g_max[dv * 3 + 2], v2);
}

__global__ void k_logits2(const int* __restrict__ a, const int* __restrict__ b) {
    int p = blockIdx.x * blockDim.x + threadIdx.x;
    if (p >= N_EDGES) return;
    int sv = g_esrc[p], dv = g_edst[p];
    float v0 = g_el2[sv * 3 + 0] + g_er2[dv * 3 + 0];
    float v1 = g_el2[sv * 3 + 1] + g_er2[dv * 3 + 1];
    float v2 = g_el2[sv * 3 + 2] + g_er2[dv * 3 + 2];
    v0 = (v0 > 0.f) ? v0 : NEG_SLOPE * v0;
    v1 = (v1 > 0.f) ? v1 : NEG_SLOPE * v1;
    v2 = (v2 > 0.f) ? v2 : NEG_SLOPE * v2;
    g_a4[p] = make_float4(v0, v1, v2, __int_as_float(sv));
    atomicMaxF(&g_max[dv * 3 + 0], v0);
    atomicMaxF(&g_max[dv * 3 + 1], v1);
    atomicMaxF(&g_max[dv * 3 + 2], v2);
}

// re-init g_max between layers
__global__ void k_remax(const int* __restrict__ dummy) {
    int i = blockIdx.x * blockDim.x + threadIdx.x;
    if (i < N_NODES * 3) g_max[i] = -INFINITY;
}

// ---------------- aggregation layer 1: warp/node, 2 LDG per edge ----------------
// lane l<24 owns dims 4l..4l+3 (head = l/8). Per edge: 1 bcast float4 (logits+src)
// + 1 coalesced float4 row segment.
__global__ void k_agg1(const int* __restrict__ dummy) {
    int n = (blockIdx.x * blockDim.x + threadIdx.x) >> 5;
    if (n >= N_NODES) return;
    int lane = threadIdx.x & 31;
    bool act = lane < 24;
    int hsel = lane >> 3; if (hsel > 2) hsel = 2;
    int b0 = g_off[n], b1 = g_off[n + 1];
    float m0 = g_max[n * 3 + 0], m1 = g_max[n * 3 + 1], m2 = g_max[n * 3 + 2];
    float s0 = 0.f, s1 = 0.f, s2 = 0.f;
    float4 acc = make_float4(0.f, 0.f, 0.f, 0.f);
#pragma unroll 2
    for (int p = b0; p < b1; p++) {
        float4 av = g_a4[p];
        int sv = __float_as_int(av.w);
        float e0 = expf(av.x - m0);
        float e1 = expf(av.y - m1);
        float e2 = expf(av.z - m2);
        float eh = (hsel == 0) ? e0 : (hsel == 1) ? e1 : e2;
        if (act) {
            float4 z = *reinterpret_cast<const float4*>(&g_z1[sv * 96 + lane * 4]);
            acc.x = fmaf(eh, z.x, acc.x);
            acc.y = fmaf(eh, z.y, acc.y);
            acc.z = fmaf(eh, z.z, acc.z);
            acc.w = fmaf(eh, z.w, acc.w);
        }
        s0 += e0; s1 += e1; s2 += e2;
    }
    if (act) {
        float sh = (hsel == 0) ? s0 : (hsel == 1) ? s1 : s2;
        float inv = 1.0f / (sh + 1e-16f);
        float4 o;
        o.x = fmaxf(acc.x * inv, 0.f);
        o.y = fmaxf(acc.y * inv, 0.f);
        o.z = fmaxf(acc.z * inv, 0.f);
        o.w = fmaxf(acc.w * inv, 0.f);
        *reinterpret_cast<float4*>(&g_x1[n * 96 + lane * 4]) = o;
    }
}

// ---------------- layer 2 el/er from relu(x1) (R12-proven) ----------------
__global__ void k_el2(const int* __restrict__ dummy) {
    int i = blockIdx.x * blockDim.x + threadIdx.x;
    if (i >= N_NODES * 3) return;
    int n = i / 3, h = i - n * 3;
    float el = 0.f, er = 0.f;
#pragma unroll 8
    for (int k = 0; k < 96; k++) {
        float x = g_x1[n * 96 + k];
        el = fmaf(x, g_w2al[h * 96 + k], el);
        er = fmaf(x, g_w2ar[h * 96 + k], er);
    }
    g_el2[i] = el; g_er2[i] = er;
}

// ---------------- aggregation layer 2: warp/node, 2 LDG per edge, 3 head-accs ----
__global__ void k_agg2u(const int* __restrict__ dummy) {
    int n = (blockIdx.x * blockDim.x + threadIdx.x) >> 5;
    if (n >= N_NODES) return;
    int lane = threadIdx.x & 31;
    bool act = lane < 24;
    int b0 = g_off[n], b1 = g_off[n + 1];
    float m0 = g_max[n * 3 + 0], m1 = g_max[n * 3 + 1], m2 = g_max[n * 3 + 2];
    float s0 = 0.f, s1 = 0.f, s2 = 0.f;
    float4 A0 = make_float4(0.f, 0.f, 0.f, 0.f);
    float4 A1 = A0, A2 = A0;
#pragma unroll 2
    for (int p = b0; p < b1; p++) {
        float4 av = g_a4[p];
        int sv = __float_as_int(av.w);
        float e0 = expf(av.x - m0);
        float e1 = expf(av.y - m1);
        float e2 = expf(av.z - m2);
        if (act) {
            float4 x = *reinterpret_cast<const float4*>(&g_x1[sv * 96 + lane * 4]);
            A0.x = fmaf(e0, x.x, A0.x); A0.y = fmaf(e0, x.y, A0.y);
            A0.z = fmaf(e0, x.z, A0.z); A0.w = fmaf(e0, x.w, A0.w);
            A1.x = fmaf(e1, x.x, A1.x); A1.y = fmaf(e1, x.y, A1.y);
            A1.z = fmaf(e1, x.z, A1.z); A1.w = fmaf(e1, x.w, A1.w);
            A2.x = fmaf(e2, x.x, A2.x); A2.y = fmaf(e2, x.y, A2.y);
            A2.z = fmaf(e2, x.z, A2.z); A2.w = fmaf(e2, x.w, A2.w);
        }
        s0 += e0; s1 += e1; s2 += e2;
    }
    if (act) {
        float i0 = 1.0f / (s0 + 1e-16f);
        float i1 = 1.0f / (s1 + 1e-16f);
        float i2 = 1.0f / (s2 + 1e-16f);
        float* u = &g_u2[n * 288];
        *reinterpret_cast<float4*>(&u[lane * 4]) =
            make_float4(A0.x * i0, A0.y * i0, A0.z * i0, A0.w * i0);
        *reinterpret_cast<float4*>(&u[96 + lane * 4]) =
            make_float4(A1.x * i1, A1.y * i1, A1.z * i1, A1.w * i1);
        *reinterpret_cast<float4*>(&u[192 + lane * 4]) =
            make_float4(A2.x * i2, A2.y * i2, A2.z * i2, A2.w * i2);
    }
}

// ---------------- gemm2 + fused pooling: x2 = u2 @ W2 per head, relu, pool ----------
#define GT 8
__global__ void k_gemm2pool(const float* __restrict__ W2, const int* __restrict__ gid) {
    __shared__ float us[GT][289];
    __shared__ int gids[GT];
    int o = threadIdx.x;            // 0..191
    int base = blockIdx.x * GT;     // 6250 full blocks
    for (int idx = threadIdx.x; idx < GT * 288; idx += 192) {
        int i = idx / 288, k = idx - i * 288;
        us[i][k] = g_u2[(base + i) * 288 + k];
    }
    if (threadIdx.x < GT) gids[threadIdx.x] = gid[base + threadIdx.x];
    __syncthreads();
    int hbase = (o >> 6) * 96;
    float acc[GT];
#pragma unroll
    for (int i = 0; i < GT; i++) acc[i] = 0.f;
    for (int k = 0; k < 96; k++) {
        float w = __ldg(&W2[k * 192 + o]);
#pragma unroll
        for (int i = 0; i < GT; i++) acc[i] = fmaf(us[i][hbase + k], w, acc[i]);
    }
    // fused pool: run-merge relu(x2) over the block's 8 sorted-gid nodes
    float run = 0.f;
    int cur = gids[0];
#pragma unroll
    for (int i = 0; i < GT; i++) {
        int g = gids[i];
        if (g != cur) {
            atomicAdd(&g_pool[cur * 192 + o], run);
            run = 0.f; cur = g;
        }
        run += fmaxf(acc[i], 0.f);
    }
    atomicAdd(&g_pool[cur * 192 + o], run);
}

// ---------------- final MLP (proven) ----------------
__global__ void k_mlp(const float* __restrict__ d1w, const float* __restrict__ d1b,
                      const float* __restrict__ d2w, const float* __restrict__ d2b,
                      float* __restrict__ out) {
    int g = blockIdx.x;
    int j = threadIdx.x;  // 0..63
    __shared__ float ps[192];
    __shared__ float hred[64];
    float inv = 1.0f / fmaxf(g_cnt[g], 1.0f);
    for (int k = j; k < 192; k += 64) ps[k] = g_pool[g * 192 + k] * inv;
    __syncthreads();
    float acc = d1b[j];
#pragma unroll 8
    for (int k = 0; k < 192; k++) acc = fmaf(ps[k], __ldg(&d1w[k * 64 + j]), acc);
    acc = fmaxf(acc, 0.f);
    hred[j] = acc * __ldg(&d2w[j]);
    __syncthreads();
    for (int s = 32; s > 0; s >>= 1) {
        if (j < s) hred[j] += hred[j + s];
        __syncthreads();
    }
    if (j == 0) out[g] = hred[0] + d2b[0];
}

// ---------------- launch ----------------
extern "C" void kernel_launch(void* const* d_in, const int* in_sizes, int n_in,
                              void* d_out, int out_size) {
    const float* feature = (const float*)d_in[0];
    const int*   src     = (const int*)d_in[1];
    const int*   dst     = (const int*)d_in[2];
    const int*   gid     = (const int*)d_in[3];
    const float* W1      = (const float*)d_in[4];
    const float* al1     = (const float*)d_in[5];
    const float* ar1     = (const float*)d_in[6];
    const float* W2      = (const float*)d_in[7];
    const float* al2     = (const float*)d_in[8];
    const float* ar2     = (const float*)d_in[9];
    const float* d1w     = (const float*)d_in[10];
    const float* d1b     = (const float*)d_in[11];
    const float* d2w     = (const float*)d_in[12];
    const float* d2b     = (const float*)d_in[13];
    float* out = (float*)d_out;

    // init + CSR build + projections
    k_init<<<(N_NODES * 3 + 255) / 256, 256>>>(dst);
    k_hist<<<(N_EDGES + 255) / 256, 256>>>(dst);
    k_scan<<<1, SCAN_T>>>(dst);
    k_scatter<<<(N_EDGES + 255) / 256, 256>>>(src, dst);
    k_cnt<<<(N_NODES + 255) / 256, 256>>>(gid);
    k_prew<<<1, 288>>>(W2, al2, ar2);

    // ---- layer 1 ----
    k_layer1_z<<<(N_NODES + 127) / 128, 128>>>(feature, W1, al1, ar1);
    k_logits1<<<(N_EDGES + 255) / 256, 256>>>(src, dst);
    k_agg1<<<(N_NODES * 32 + 255) / 256, 256>>>(src);

    // ---- layer 2 ----
    k_el2<<<(N_NODES * 3 + 255) / 256, 256>>>(src);
    k_remax<<<(N_NODES * 3 + 255) / 256, 256>>>(dst);
    k_logits2<<<(N_EDGES + 255) / 256, 256>>>(src, dst);
    k_agg2u<<<(N_NODES * 32 + 255) / 256, 256>>>(src);
    k_gemm2pool<<<N_NODES / GT, 192>>>(W2, gid);

    // ---- MLP ----
    k_mlp<<<N_GRAPHS, 64>>>(d1w, d1b, d2w, d2b, out);
}

// round 14
// speedup vs baseline: 1.4020x; 1.1008x over previous
#include <cuda_runtime.h>
#include <math.h>

#define N_NODES 50000
#define N_EDGES 800000
#define N_GRAPHS 128
#define NEG_SLOPE 0.2f

// ---------------- scratch (device globals) ----------------
__device__ float g_el1[N_NODES * 3];
__device__ float g_er1[N_NODES * 3];
__device__ __align__(16) float g_x1[N_NODES * 96];    // POST-relu layer-1 output

__device__ float g_el2[N_NODES * 3];
__device__ float g_er2[N_NODES * 3];
__device__ __align__(16) float g_u2[N_NODES * 288];   // aggregated relu(x1) per head

__device__ __align__(16) float4 g_a4[N_EDGES];        // {v0,v1,v2, bits(src)} per sorted edge
__device__ float g_max[N_NODES * 3];

__device__ float g_w1al[30], g_w1ar[30];              // W1 @ al1 / ar1   [h][d<10]
__device__ float g_w2al[288], g_w2ar[288];            // W2 @ al2 / ar2   [h][k<96]

__device__ float g_pool[N_GRAPHS * 192];
__device__ float g_cnt[N_GRAPHS];

// CSR scratch
__device__ int g_deg[N_NODES];
__device__ int g_off[N_NODES + 1];
__device__ int g_cur[N_NODES];
__device__ int g_esrc[N_EDGES];
__device__ int g_edst[N_EDGES];

// ---------------- init ----------------
__global__ void k_init(const int* __restrict__ dummy) {
    int i = blockIdx.x * blockDim.x + threadIdx.x;
    if (i < N_NODES) g_deg[i] = 0;
    if (i < N_NODES * 3) g_max[i] = -INFINITY;
    if (i < N_GRAPHS * 192) g_pool[i] = 0.0f;
    if (i < N_GRAPHS)       g_cnt[i] = 0.0f;
}

// ---------------- CSR build (proven) ----------------
__global__ void k_hist(const int* __restrict__ dst) {
    int e = blockIdx.x * blockDim.x + threadIdx.x;
    if (e < N_EDGES) atomicAdd(&g_deg[dst[e]], 1);
}

#define SCAN_T 256
#define SCAN_CHUNK ((N_NODES + SCAN_T - 1) / SCAN_T)
__global__ void k_scan(const int* __restrict__ dst_unused) {
    __shared__ int psum[SCAN_T];
    int t = threadIdx.x;
    int lo = t * SCAN_CHUNK;
    int hi = (lo + SCAN_CHUNK < N_NODES) ? (lo + SCAN_CHUNK) : N_NODES;
    int s = 0;
    for (int n = lo; n < hi; n++) s += g_deg[n];
    psum[t] = s;
    __syncthreads();
    if (t == 0) {
        int run = 0;
        for (int i = 0; i < SCAN_T; i++) { int tmp = psum[i]; psum[i] = run; run += tmp; }
    }
    __syncthreads();
    int run = psum[t];
    for (int n = lo; n < hi; n++) {
        g_off[n] = run;
        g_cur[n] = run;
        run += g_deg[n];
    }
    if (t == 0) g_off[N_NODES] = N_EDGES;
}

__global__ void k_scatter(const int* __restrict__ src, const int* __restrict__ dst) {
    int e = blockIdx.x * blockDim.x + threadIdx.x;
    if (e < N_EDGES) {
        int d = dst[e];
        int p = atomicAdd(&g_cur[d], 1);
        g_esrc[p] = src[e];
        g_edst[p] = d;
    }
}

__global__ void k_cnt(const int* __restrict__ gid) {
    int n = blockIdx.x * blockDim.x + threadIdx.x;
    if (n < N_NODES) atomicAdd(&g_cnt[gid[n]], 1.0f);
}

// ---------------- helpers ----------------
__device__ __forceinline__ void atomicMaxF(float* addr, float v) {
    if (v >= 0.0f) atomicMax((int*)addr, __float_as_int(v));
    else           atomicMin((unsigned int*)addr, __float_as_uint(v));
}

// ---------------- precompute projected attention vectors (R11-proven algebra) ----
__global__ void k_prew(const float* __restrict__ W1, const float* __restrict__ al1,
                       const float* __restrict__ ar1, const float* __restrict__ W2,
                       const float* __restrict__ al2, const float* __restrict__ ar2) {
    int t = threadIdx.x;   // 288 threads
    if (t < 30) {
        int h = t / 10, d = t - 10 * h;
        float sl = 0.f, sr = 0.f;
#pragma unroll
        for (int j = 0; j < 32; j++) {
            float w = W1[d * 96 + h * 32 + j];
            sl = fmaf(w, al1[h * 32 + j], sl);
            sr = fmaf(w, ar1[h * 32 + j], sr);
        }
        g_w1al[t] = sl; g_w1ar[t] = sr;
    }
    if (t < 288) {
        int h = t / 96, k = t - 96 * h;
        float sl = 0.f, sr = 0.f;
#pragma unroll 8
        for (int j = 0; j < 64; j++) {
            float w = W2[k * 192 + h * 64 + j];
            sl = fmaf(w, al2[h * 64 + j], sl);
            sr = fmaf(w, ar2[h * 64 + j], sr);
        }
        g_w2al[t] = sl; g_w2ar[t] = sr;
    }
}

// ---------------- layer 1 el/er directly from features (R11-proven) ----------------
__global__ void k_el1(const float* __restrict__ feat) {
    int n = blockIdx.x * blockDim.x + threadIdx.x;
    if (n >= N_NODES) return;
    float f[10];
#pragma unroll
    for (int d = 0; d < 10; d++) f[d] = feat[n * 10 + d];
#pragma unroll
    for (int h = 0; h < 3; h++) {
        float el = 0.f, er = 0.f;
#pragma unroll
        for (int d = 0; d < 10; d++) {
            el = fmaf(f[d], g_w1al[h * 10 + d], el);
            er = fmaf(f[d], g_w1ar[h * 10 + d], er);
        }
        g_el1[n * 3 + h] = el;
        g_er1[n * 3 + h] = er;
    }
}

// ---------------- logits: thread per edge, 3 heads, packed float4 store (proven) ----
__global__ void k_logits1(const int* __restrict__ a, const int* __restrict__ b) {
    int p = blockIdx.x * blockDim.x + threadIdx.x;
    if (p >= N_EDGES) return;
    int sv = g_esrc[p], dv = g_edst[p];
    float v0 = g_el1[sv * 3 + 0] + g_er1[dv * 3 + 0];
    float v1 = g_el1[sv * 3 + 1] + g_er1[dv * 3 + 1];
    float v2 = g_el1[sv * 3 + 2] + g_er1[dv * 3 + 2];
    v0 = (v0 > 0.f) ? v0 : NEG_SLOPE * v0;
    v1 = (v1 > 0.f) ? v1 : NEG_SLOPE * v1;
    v2 = (v2 > 0.f) ? v2 : NEG_SLOPE * v2;
    g_a4[p] = make_float4(v0, v1, v2, __int_as_float(sv));
    atomicMaxF(&g_max[dv * 3 + 0], v0);
    atomicMaxF(&g_max[dv * 3 + 1], v1);
    atomicMaxF(&g_max[dv * 3 + 2], v2);
}

__global__ void k_logits2(const int* __restrict__ a, const int* __restrict__ b) {
    int p = blockIdx.x * blockDim.x + threadIdx.x;
    if (p >= N_EDGES) return;
    int sv = g_esrc[p], dv = g_edst[p];
    float v0 = g_el2[sv * 3 + 0] + g_er2[dv * 3 + 0];
    float v1 = g_el2[sv * 3 + 1] + g_er2[dv * 3 + 1];
    float v2 = g_el2[sv * 3 + 2] + g_er2[dv * 3 + 2];
    v0 = (v0 > 0.f) ? v0 : NEG_SLOPE * v0;
    v1 = (v1 > 0.f) ? v1 : NEG_SLOPE * v1;
    v2 = (v2 > 0.f) ? v2 : NEG_SLOPE * v2;
    g_a4[p] = make_float4(v0, v1, v2, __int_as_float(sv));
    atomicMaxF(&g_max[dv * 3 + 0], v0);
    atomicMaxF(&g_max[dv * 3 + 1], v1);
    atomicMaxF(&g_max[dv * 3 + 2], v2);
}

// re-init g_max between layers
__global__ void k_remax(const int* __restrict__ dummy) {
    int i = blockIdx.x * blockDim.x + threadIdx.x;
    if (i < N_NODES * 3) g_max[i] = -INFINITY;
}

// ---------------- aggregation layer 1 COMMUTED: warp/node over FEATURE rows ----
// Per edge: 1 sector a4 bcast + 2 sectors feature row (40B, read by 3 lane-groups).
// Lane l<30 owns (h=l/10, d=l%10): u[h][d] = (sum_e e_h * f[src][d]) / s_h.
// Then per-warp mini-GEMM u @ W1 -> x1 row (relu fused). No cross-warp sync.
__global__ void k_agg1c(const float* __restrict__ feat, const float* __restrict__ W1) {
    __shared__ float u1s[8][32];
    int wid = threadIdx.x >> 5, lane = threadIdx.x & 31;
    int n = (blockIdx.x * blockDim.x + threadIdx.x) >> 5;   // grid exactly covers 50000
    bool act = lane < 30;
    int hsel = lane / 10; if (hsel > 2) hsel = 2;
    int d = lane - hsel * 10; if (!act) d = 0;
    int b0 = g_off[n], b1 = g_off[n + 1];
    float m0 = g_max[n * 3 + 0], m1 = g_max[n * 3 + 1], m2 = g_max[n * 3 + 2];
    float s0 = 0.f, s1 = 0.f, s2 = 0.f, acc = 0.f;
#pragma unroll 2
    for (int p = b0; p < b1; p++) {
        float4 av = g_a4[p];
        int sv = __float_as_int(av.w);
        float e0 = expf(av.x - m0);
        float e1 = expf(av.y - m1);
        float e2 = expf(av.z - m2);
        float eh = (hsel == 0) ? e0 : (hsel == 1) ? e1 : e2;
        float fv = act ? feat[sv * 10 + d] : 0.f;
        acc = fmaf(eh, fv, acc);
        s0 += e0; s1 += e1; s2 += e2;
    }
    float sh = (hsel == 0) ? s0 : (hsel == 1) ? s1 : s2;
    u1s[wid][lane] = acc / (sh + 1e-16f);
    __syncwarp();
    // mini-GEMM: lane produces outputs o = lane + 32t, head = t
#pragma unroll
    for (int t = 0; t < 3; t++) {
        int o = lane + (t << 5);
        float x = 0.f;
#pragma unroll
        for (int dd = 0; dd < 10; dd++)
            x = fmaf(u1s[wid][t * 10 + dd], __ldg(&W1[dd * 96 + o]), x);
        g_x1[n * 96 + o] = fmaxf(x, 0.f);    // relu fused
    }
}

// ---------------- layer 2 el/er from relu(x1) (proven) ----------------
__global__ void k_el2(const int* __restrict__ dummy) {
    int i = blockIdx.x * blockDim.x + threadIdx.x;
    if (i >= N_NODES * 3) return;
    int n = i / 3, h = i - n * 3;
    float el = 0.f, er = 0.f;
#pragma unroll 8
    for (int k = 0; k < 96; k++) {
        float x = g_x1[n * 96 + k];
        el = fmaf(x, g_w2al[h * 96 + k], el);
        er = fmaf(x, g_w2ar[h * 96 + k], er);
    }
    g_el2[i] = el; g_er2[i] = er;
}

// ---------------- aggregation layer 2 (R13-proven): warp/node, float4 gather ----
__global__ void k_agg2u(const int* __restrict__ dummy) {
    int n = (blockIdx.x * blockDim.x + threadIdx.x) >> 5;
    if (n >= N_NODES) return;
    int lane = threadIdx.x & 31;
    bool act = lane < 24;
    int b0 = g_off[n], b1 = g_off[n + 1];
    float m0 = g_max[n * 3 + 0], m1 = g_max[n * 3 + 1], m2 = g_max[n * 3 + 2];
    float s0 = 0.f, s1 = 0.f, s2 = 0.f;
    float4 A0 = make_float4(0.f, 0.f, 0.f, 0.f);
    float4 A1 = A0, A2 = A0;
#pragma unroll 2
    for (int p = b0; p < b1; p++) {
        float4 av = g_a4[p];
        int sv = __float_as_int(av.w);
        float e0 = expf(av.x - m0);
        float e1 = expf(av.y - m1);
        float e2 = expf(av.z - m2);
        if (act) {
            float4 x = *reinterpret_cast<const float4*>(&g_x1[sv * 96 + lane * 4]);
            A0.x = fmaf(e0, x.x, A0.x); A0.y = fmaf(e0, x.y, A0.y);
            A0.z = fmaf(e0, x.z, A0.z); A0.w = fmaf(e0, x.w, A0.w);
            A1.x = fmaf(e1, x.x, A1.x); A1.y = fmaf(e1, x.y, A1.y);
            A1.z = fmaf(e1, x.z, A1.z); A1.w = fmaf(e1, x.w, A1.w);
            A2.x = fmaf(e2, x.x, A2.x); A2.y = fmaf(e2, x.y, A2.y);
            A2.z = fmaf(e2, x.z, A2.z); A2.w = fmaf(e2, x.w, A2.w);
        }
        s0 += e0; s1 += e1; s2 += e2;
    }
    if (act) {
        float i0 = 1.0f / (s0 + 1e-16f);
        float i1 = 1.0f / (s1 + 1e-16f);
        float i2 = 1.0f / (s2 + 1e-16f);
        float* u = &g_u2[n * 288];
        *reinterpret_cast<float4*>(&u[lane * 4]) =
            make_float4(A0.x * i0, A0.y * i0, A0.z * i0, A0.w * i0);
        *reinterpret_cast<float4*>(&u[96 + lane * 4]) =
            make_float4(A1.x * i1, A1.y * i1, A1.z * i1, A1.w * i1);
        *reinterpret_cast<float4*>(&u[192 + lane * 4]) =
            make_float4(A2.x * i2, A2.y * i2, A2.z * i2, A2.w * i2);
    }
}

// ---------------- gemm2 + fused pooling (R13-proven) ----------
#define GT 8
__global__ void k_gemm2pool(const float* __restrict__ W2, const int* __restrict__ gid) {
    __shared__ float us[GT][289];
    __shared__ int gids[GT];
    int o = threadIdx.x;            // 0..191
    int base = blockIdx.x * GT;     // 6250 full blocks
    for (int idx = threadIdx.x; idx < GT * 288; idx += 192) {
        int i = idx / 288, k = idx - i * 288;
        us[i][k] = g_u2[(base + i) * 288 + k];
    }
    if (threadIdx.x < GT) gids[threadIdx.x] = gid[base + threadIdx.x];
    __syncthreads();
    int hbase = (o >> 6) * 96;
    float acc[GT];
#pragma unroll
    for (int i = 0; i < GT; i++) acc[i] = 0.f;
    for (int k = 0; k < 96; k++) {
        float w = __ldg(&W2[k * 192 + o]);
#pragma unroll
        for (int i = 0; i < GT; i++) acc[i] = fmaf(us[i][hbase + k], w, acc[i]);
    }
    float run = 0.f;
    int cur = gids[0];
#pragma unroll
    for (int i = 0; i < GT; i++) {
        int g = gids[i];
        if (g != cur) {
            atomicAdd(&g_pool[cur * 192 + o], run);
            run = 0.f; cur = g;
        }
        run += fmaxf(acc[i], 0.f);
    }
    atomicAdd(&g_pool[cur * 192 + o], run);
}

// ---------------- final MLP (proven) ----------------
__global__ void k_mlp(const float* __restrict__ d1w, const float* __restrict__ d1b,
                      const float* __restrict__ d2w, const float* __restrict__ d2b,
                      float* __restrict__ out) {
    int g = blockIdx.x;
    int j = threadIdx.x;  // 0..63
    __shared__ float ps[192];
    __shared__ float hred[64];
    float inv = 1.0f / fmaxf(g_cnt[g], 1.0f);
    for (int k = j; k < 192; k += 64) ps[k] = g_pool[g * 192 + k] * inv;
    __syncthreads();
    float acc = d1b[j];
#pragma unroll 8
    for (int k = 0; k < 192; k++) acc = fmaf(ps[k], __ldg(&d1w[k * 64 + j]), acc);
    acc = fmaxf(acc, 0.f);
    hred[j] = acc * __ldg(&d2w[j]);
    __syncthreads();
    for (int s = 32; s > 0; s >>= 1) {
        if (j < s) hred[j] += hred[j + s];
        __syncthreads();
    }
    if (j == 0) out[g] = hred[0] + d2b[0];
}

// ---------------- launch ----------------
extern "C" void kernel_launch(void* const* d_in, const int* in_sizes, int n_in,
                              void* d_out, int out_size) {
    const float* feature = (const float*)d_in[0];
    const int*   src     = (const int*)d_in[1];
    const int*   dst     = (const int*)d_in[2];
    const int*   gid     = (const int*)d_in[3];
    const float* W1      = (const float*)d_in[4];
    const float* al1     = (const float*)d_in[5];
    const float* ar1     = (const float*)d_in[6];
    const float* W2      = (const float*)d_in[7];
    const float* al2     = (const float*)d_in[8];
    const float* ar2     = (const float*)d_in[9];
    const float* d1w     = (const float*)d_in[10];
    const float* d1b     = (const float*)d_in[11];
    const float* d2w     = (const float*)d_in[12];
    const float* d2b     = (const float*)d_in[13];
    float* out = (float*)d_out;

    // init + CSR build + projections
    k_init<<<(N_NODES * 3 + 255) / 256, 256>>>(dst);
    k_hist<<<(N_EDGES + 255) / 256, 256>>>(dst);
    k_scan<<<1, SCAN_T>>>(dst);
    k_scatter<<<(N_EDGES + 255) / 256, 256>>>(src, dst);
    k_cnt<<<(N_NODES + 255) / 256, 256>>>(gid);
    k_prew<<<1, 288>>>(W1, al1, ar1, W2, al2, ar2);

    // ---- layer 1 (commuted GEMM: aggregate 10-dim features) ----
    k_el1<<<(N_NODES + 255) / 256, 256>>>(feature);
    k_logits1<<<(N_EDGES + 255) / 256, 256>>>(src, dst);
    k_agg1c<<<N_NODES / 8, 256>>>(feature, W1);    // 6250 full blocks, warp/node

    // ---- layer 2 (proven path) ----
    k_el2<<<(N_NODES * 3 + 255) / 256, 256>>>(src);
    k_remax<<<(N_NODES * 3 + 255) / 256, 256>>>(dst);
    k_logits2<<<(N_EDGES + 255) / 256, 256>>>(src, dst);
    k_agg2u<<<(N_NODES * 32 + 255) / 256, 256>>>(src);
    k_gemm2pool<<<N_NODES / GT, 192>>>(W2, gid);

    // ---- MLP ----
    k_mlp<<<N_GRAPHS, 64>>>(d1w, d1b, d2w, d2b, out);
}

// round 15
// speedup vs baseline: 1.6383x; 1.1686x over previous
#include <cuda_runtime.h>
#include <math.h>

#define N_NODES 50000
#define N_EDGES 800000
#define N_GRAPHS 128
#define NEG_SLOPE 0.2f

// ---------------- scratch (device globals) ----------------
__device__ float g_el1[N_NODES * 3];
__device__ float g_er1[N_NODES * 3];
__device__ __align__(16) float g_x1[N_NODES * 96];    // POST-relu layer-1 output

__device__ float g_el2[N_NODES * 3];
__device__ float g_er2[N_NODES * 3];
__device__ __align__(16) float g_u2[N_NODES * 288];   // aggregated relu(x1) per head

__device__ __align__(16) float4 g_a4[N_EDGES];        // {w0,w1,w2, bits(src)}: w = exp(leaky(logit))

__device__ float g_w1al[30], g_w1ar[30];              // W1 @ al1 / ar1   [h][d<10]
__device__ float g_w2al[288], g_w2ar[288];            // W2 @ al2 / ar2   [h][k<96]

__device__ float g_pool[N_GRAPHS * 192];
__device__ float g_cnt[N_GRAPHS];

// CSR scratch
__device__ int g_deg[N_NODES];
__device__ int g_off[N_NODES + 1];
__device__ int g_cur[N_NODES];
__device__ int g_esrc[N_EDGES];
__device__ int g_edst[N_EDGES];

// ---------------- init ----------------
__global__ void k_init(const int* __restrict__ dummy) {
    int i = blockIdx.x * blockDim.x + threadIdx.x;
    if (i < N_NODES) g_deg[i] = 0;
    if (i < N_GRAPHS * 192) g_pool[i] = 0.0f;
    if (i < N_GRAPHS)       g_cnt[i] = 0.0f;
}

// ---------------- CSR build (proven) ----------------
__global__ void k_hist(const int* __restrict__ dst) {
    int e = blockIdx.x * blockDim.x + threadIdx.x;
    if (e < N_EDGES) atomicAdd(&g_deg[dst[e]], 1);
}

#define SCAN_T 256
#define SCAN_CHUNK ((N_NODES + SCAN_T - 1) / SCAN_T)
__global__ void k_scan(const int* __restrict__ dst_unused) {
    __shared__ int psum[SCAN_T];
    int t = threadIdx.x;
    int lo = t * SCAN_CHUNK;
    int hi = (lo + SCAN_CHUNK < N_NODES) ? (lo + SCAN_CHUNK) : N_NODES;
    int s = 0;
    for (int n = lo; n < hi; n++) s += g_deg[n];
    psum[t] = s;
    __syncthreads();
    if (t == 0) {
        int run = 0;
        for (int i = 0; i < SCAN_T; i++) { int tmp = psum[i]; psum[i] = run; run += tmp; }
    }
    __syncthreads();
    int run = psum[t];
    for (int n = lo; n < hi; n++) {
        g_off[n] = run;
        g_cur[n] = run;
        run += g_deg[n];
    }
    if (t == 0) g_off[N_NODES] = N_EDGES;
}

__global__ void k_scatter(const int* __restrict__ src, const int* __restrict__ dst) {
    int e = blockIdx.x * blockDim.x + threadIdx.x;
    if (e < N_EDGES) {
        int d = dst[e];
        int p = atomicAdd(&g_cur[d], 1);
        g_esrc[p] = src[e];
        g_edst[p] = d;
    }
}

__global__ void k_cnt(const int* __restrict__ gid) {
    int n = blockIdx.x * blockDim.x + threadIdx.x;
    if (n < N_NODES) atomicAdd(&g_cnt[gid[n]], 1.0f);
}

// ---------------- precompute projected attention vectors (proven) ----------------
__global__ void k_prew(const float* __restrict__ W1, const float* __restrict__ al1,
                       const float* __restrict__ ar1, const float* __restrict__ W2,
                       const float* __restrict__ al2, const float* __restrict__ ar2) {
    int t = threadIdx.x;   // 288 threads
    if (t < 30) {
        int h = t / 10, d = t - 10 * h;
        float sl = 0.f, sr = 0.f;
#pragma unroll
        for (int j = 0; j < 32; j++) {
            float w = W1[d * 96 + h * 32 + j];
            sl = fmaf(w, al1[h * 32 + j], sl);
            sr = fmaf(w, ar1[h * 32 + j], sr);
        }
        g_w1al[t] = sl; g_w1ar[t] = sr;
    }
    if (t < 288) {
        int h = t / 96, k = t - 96 * h;
        float sl = 0.f, sr = 0.f;
#pragma unroll 8
        for (int j = 0; j < 64; j++) {
            float w = W2[k * 192 + h * 64 + j];
            sl = fmaf(w, al2[h * 64 + j], sl);
            sr = fmaf(w, ar2[h * 64 + j], sr);
        }
        g_w2al[t] = sl; g_w2ar[t] = sr;
    }
}

// ---------------- layer 1 el/er directly from features (proven) ----------------
__global__ void k_el1(const float* __restrict__ feat) {
    int n = blockIdx.x * blockDim.x + threadIdx.x;
    if (n >= N_NODES) return;
    float f[10];
#pragma unroll
    for (int d = 0; d < 10; d++) f[d] = feat[n * 10 + d];
#pragma unroll
    for (int h = 0; h < 3; h++) {
        float el = 0.f, er = 0.f;
#pragma unroll
        for (int d = 0; d < 10; d++) {
            el = fmaf(f[d], g_w1al[h * 10 + d], el);
            er = fmaf(f[d], g_w1ar[h * 10 + d], er);
        }
        g_el1[n * 3 + h] = el;
        g_er1[n * 3 + h] = er;
    }
}

// ---------------- logits: thread/edge; store exp(leaky(v)) packed; NO atomics ----
// softmax shift-invariance: exp(v)/sum(exp(v)) == exp(v-m)/sum — max pass removed.
__global__ void k_logits1(const int* __restrict__ a, const int* __restrict__ b) {
    int p = blockIdx.x * blockDim.x + threadIdx.x;
    if (p >= N_EDGES) return;
    int sv = g_esrc[p], dv = g_edst[p];
    float v0 = g_el1[sv * 3 + 0] + g_er1[dv * 3 + 0];
    float v1 = g_el1[sv * 3 + 1] + g_er1[dv * 3 + 1];
    float v2 = g_el1[sv * 3 + 2] + g_er1[dv * 3 + 2];
    v0 = (v0 > 0.f) ? v0 : NEG_SLOPE * v0;
    v1 = (v1 > 0.f) ? v1 : NEG_SLOPE * v1;
    v2 = (v2 > 0.f) ? v2 : NEG_SLOPE * v2;
    g_a4[p] = make_float4(expf(v0), expf(v1), expf(v2), __int_as_float(sv));
}

__global__ void k_logits2(const int* __restrict__ a, const int* __restrict__ b) {
    int p = blockIdx.x * blockDim.x + threadIdx.x;
    if (p >= N_EDGES) return;
    int sv = g_esrc[p], dv = g_edst[p];
    float v0 = g_el2[sv * 3 + 0] + g_er2[dv * 3 + 0];
    float v1 = g_el2[sv * 3 + 1] + g_er2[dv * 3 + 1];
    float v2 = g_el2[sv * 3 + 2] + g_er2[dv * 3 + 2];
    v0 = (v0 > 0.f) ? v0 : NEG_SLOPE * v0;
    v1 = (v1 > 0.f) ? v1 : NEG_SLOPE * v1;
    v2 = (v2 > 0.f) ? v2 : NEG_SLOPE * v2;
    g_a4[p] = make_float4(expf(v0), expf(v1), expf(v2), __int_as_float(sv));
}

// ---------------- aggregation layer 1 COMMUTED (proven structure); pure LDG+FMA ----
__global__ void k_agg1c(const float* __restrict__ feat, const float* __restrict__ W1) {
    __shared__ float u1s[8][32];
    int wid = threadIdx.x >> 5, lane = threadIdx.x & 31;
    int n = (blockIdx.x * blockDim.x + threadIdx.x) >> 5;   // grid exactly covers 50000
    bool act = lane < 30;
    int hsel = lane / 10; if (hsel > 2) hsel = 2;
    int d = lane - hsel * 10; if (!act) d = 0;
    int b0 = g_off[n], b1 = g_off[n + 1];
    float s0 = 0.f, s1 = 0.f, s2 = 0.f, acc = 0.f;
#pragma unroll 2
    for (int p = b0; p < b1; p++) {
        float4 av = g_a4[p];
        int sv = __float_as_int(av.w);
        float eh = (hsel == 0) ? av.x : (hsel == 1) ? av.y : av.z;
        float fv = act ? feat[sv * 10 + d] : 0.f;
        acc = fmaf(eh, fv, acc);
        s0 += av.x; s1 += av.y; s2 += av.z;
    }
    float sh = (hsel == 0) ? s0 : (hsel == 1) ? s1 : s2;
    u1s[wid][lane] = acc / (sh + 1e-16f);
    __syncwarp();
#pragma unroll
    for (int t = 0; t < 3; t++) {
        int o = lane + (t << 5);
        float x = 0.f;
#pragma unroll
        for (int dd = 0; dd < 10; dd++)
            x = fmaf(u1s[wid][t * 10 + dd], __ldg(&W1[dd * 96 + o]), x);
        g_x1[n * 96 + o] = fmaxf(x, 0.f);    // relu fused
    }
}

// ---------------- layer 2 el/er from relu(x1) (proven) ----------------
__global__ void k_el2(const int* __restrict__ dummy) {
    int i = blockIdx.x * blockDim.x + threadIdx.x;
    if (i >= N_NODES * 3) return;
    int n = i / 3, h = i - n * 3;
    float el = 0.f, er = 0.f;
#pragma unroll 8
    for (int k = 0; k < 96; k++) {
        float x = g_x1[n * 96 + k];
        el = fmaf(x, g_w2al[h * 96 + k], el);
        er = fmaf(x, g_w2ar[h * 96 + k], er);
    }
    g_el2[i] = el; g_er2[i] = er;
}

// ---------------- aggregation layer 2 (proven structure); pure LDG+FMA ----------
__global__ void k_agg2u(const int* __restrict__ dummy) {
    int n = (blockIdx.x * blockDim.x + threadIdx.x) >> 5;
    if (n >= N_NODES) return;
    int lane = threadIdx.x & 31;
    bool act = lane < 24;
    int b0 = g_off[n], b1 = g_off[n + 1];
    float s0 = 0.f, s1 = 0.f, s2 = 0.f;
    float4 A0 = make_float4(0.f, 0.f, 0.f, 0.f);
    float4 A1 = A0, A2 = A0;
#pragma unroll 2
    for (int p = b0; p < b1; p++) {
        float4 av = g_a4[p];
        int sv = __float_as_int(av.w);
        if (act) {
            float4 x = *reinterpret_cast<const float4*>(&g_x1[sv * 96 + lane * 4]);
            A0.x = fmaf(av.x, x.x, A0.x); A0.y = fmaf(av.x, x.y, A0.y);
            A0.z = fmaf(av.x, x.z, A0.z); A0.w = fmaf(av.x, x.w, A0.w);
            A1.x = fmaf(av.y, x.x, A1.x); A1.y = fmaf(av.y, x.y, A1.y);
            A1.z = fmaf(av.y, x.z, A1.z); A1.w = fmaf(av.y, x.w, A1.w);
            A2.x = fmaf(av.z, x.x, A2.x); A2.y = fmaf(av.z, x.y, A2.y);
            A2.z = fmaf(av.z, x.z, A2.z); A2.w = fmaf(av.z, x.w, A2.w);
        }
        s0 += av.x; s1 += av.y; s2 += av.z;
    }
    if (act) {
        float i0 = 1.0f / (s0 + 1e-16f);
        float i1 = 1.0f / (s1 + 1e-16f);
        float i2 = 1.0f / (s2 + 1e-16f);
        float* u = &g_u2[n * 288];
        *reinterpret_cast<float4*>(&u[lane * 4]) =
            make_float4(A0.x * i0, A0.y * i0, A0.z * i0, A0.w * i0);
        *reinterpret_cast<float4*>(&u[96 + lane * 4]) =
            make_float4(A1.x * i1, A1.y * i1, A1.z * i1, A1.w * i1);
        *reinterpret_cast<float4*>(&u[192 + lane * 4]) =
            make_float4(A2.x * i2, A2.y * i2, A2.z * i2, A2.w * i2);
    }
}

// ---------------- gemm2 + fused pooling; k-unroll x2 with float2 smem reads ----------
#define GT 8
__global__ void k_gemm2pool(const float* __restrict__ W2, const int* __restrict__ gid) {
    __shared__ float us[GT][290];   // even pad -> 8B-aligned float2 at even k
    __shared__ int gids[GT];
    int o = threadIdx.x;            // 0..191
    int base = blockIdx.x * GT;     // 6250 full blocks
    for (int idx = threadIdx.x; idx < GT * 288; idx += 192) {
        int i = idx / 288, k = idx - i * 288;
        us[i][k] = g_u2[(base + i) * 288 + k];
    }
    if (threadIdx.x < GT) gids[threadIdx.x] = gid[base + threadIdx.x];
    __syncthreads();
    int hbase = (o >> 6) * 96;
    float acc[GT];
#pragma unroll
    for (int i = 0; i < GT; i++) acc[i] = 0.f;
    for (int k = 0; k < 96; k += 2) {
        float w0 = __ldg(&W2[k * 192 + o]);
        float w1 = __ldg(&W2[(k + 1) * 192 + o]);
#pragma unroll
        for (int i = 0; i < GT; i++) {
            float2 uv = *reinterpret_cast<const float2*>(&us[i][hbase + k]);
            acc[i] = fmaf(uv.x, w0, acc[i]);
            acc[i] = fmaf(uv.y, w1, acc[i]);
        }
    }
    float run = 0.f;
    int cur = gids[0];
#pragma unroll
    for (int i = 0; i < GT; i++) {
        int g = gids[i];
        if (g != cur) {
            atomicAdd(&g_pool[cur * 192 + o], run);
            run = 0.f; cur = g;
        }
        run += fmaxf(acc[i], 0.f);
    }
    atomicAdd(&g_pool[cur * 192 + o], run);
}

// ---------------- final MLP (proven) ----------------
__global__ void k_mlp(const float* __restrict__ d1w, const float* __restrict__ d1b,
                      const float* __restrict__ d2w, const float* __restrict__ d2b,
                      float* __restrict__ out) {
    int g = blockIdx.x;
    int j = threadIdx.x;  // 0..63
    __shared__ float ps[192];
    __shared__ float hred[64];
    float inv = 1.0f / fmaxf(g_cnt[g], 1.0f);
    for (int k = j; k < 192; k += 64) ps[k] = g_pool[g * 192 + k] * inv;
    __syncthreads();
    float acc = d1b[j];
#pragma unroll 8
    for (int k = 0; k < 192; k++) acc = fmaf(ps[k], __ldg(&d1w[k * 64 + j]), acc);
    acc = fmaxf(acc, 0.f);
    hred[j] = acc * __ldg(&d2w[j]);
    __syncthreads();
    for (int s = 32; s > 0; s >>= 1) {
        if (j < s) hred[j] += hred[j + s];
        __syncthreads();
    }
    if (j == 0) out[g] = hred[0] + d2b[0];
}

// ---------------- launch ----------------
extern "C" void kernel_launch(void* const* d_in, const int* in_sizes, int n_in,
                              void* d_out, int out_size) {
    const float* feature = (const float*)d_in[0];
    const int*   src     = (const int*)d_in[1];
    const int*   dst     = (const int*)d_in[2];
    const int*   gid     = (const int*)d_in[3];
    const float* W1      = (const float*)d_in[4];
    const float* al1     = (const float*)d_in[5];
    const float* ar1     = (const float*)d_in[6];
    const float* W2      = (const float*)d_in[7];
    const float* al2     = (const float*)d_in[8];
    const float* ar2     = (const float*)d_in[9];
    const float* d1w     = (const float*)d_in[10];
    const float* d1b     = (const float*)d_in[11];
    const float* d2w     = (const float*)d_in[12];
    const float* d2b     = (const float*)d_in[13];
    float* out = (float*)d_out;

    // init + CSR build + projections
    k_init<<<(N_NODES + 255) / 256, 256>>>(dst);
    k_hist<<<(N_EDGES + 255) / 256, 256>>>(dst);
    k_scan<<<1, SCAN_T>>>(dst);
    k_scatter<<<(N_EDGES + 255) / 256, 256>>>(src, dst);
    k_cnt<<<(N_NODES + 255) / 256, 256>>>(gid);
    k_prew<<<1, 288>>>(W1, al1, ar1, W2, al2, ar2);

    // ---- layer 1 (commuted GEMM; exp precomputed in logits) ----
    k_el1<<<(N_NODES + 255) / 256, 256>>>(feature);
    k_logits1<<<(N_EDGES + 255) / 256, 256>>>(src, dst);
    k_agg1c<<<N_NODES / 8, 256>>>(feature, W1);

    // ---- layer 2 ----
    k_el2<<<(N_NODES * 3 + 255) / 256, 256>>>(src);
    k_logits2<<<(N_EDGES + 255) / 256, 256>>>(src, dst);
    k_agg2u<<<(N_NODES * 32 + 255) / 256, 256>>>(src);
    k_gemm2pool<<<N_NODES / GT, 192>>>(W2, gid);

    // ---- MLP ----
    k_mlp<<<N_GRAPHS, 64>>>(d1w, d1b, d2w, d2b, out);
}